// round 3
// baseline (speedup 1.0000x reference)
#include <cuda_runtime.h>
#include <cuda_fp16.h>

#define N_NODES  100000
#define N_EDGES  3200000
#define N_GRAPHS 128

// ---------------- scratch (static device globals; no runtime alloc) ----------
__device__ int   g_cnt[N_NODES];
__device__ int   g_rowptr[N_NODES + 1];
__device__ int   g_fill[N_NODES];
__device__ int   g_bsums[128];
__device__ float g_dinv[N_NODES];
__device__ __align__(16) int2 g_csr[N_EDGES];      // {src, float_bits(norm_w)}
__device__ __align__(16) float g_bufa[N_NODES * 64];   // agg output (fp32, sequential)
__device__ __align__(16) __half g_h16a[N_NODES * 64];  // activations fp16 (layers 1,3)
__device__ __align__(16) __half g_h16b[N_NODES * 64];  // activations fp16 (layer 2)
__device__ __align__(16) float g_pool[N_GRAPHS * 64];

// half(nonneg)->float bit tricks; value is 2^-112 * true, weight pre-scaled by 2^112.
// (valid because activations are post-ReLU, sign bit always 0; exact incl. subnormals)
__device__ __forceinline__ float h2f_lo(unsigned v) { return __int_as_float((v & 0xffffu) << 13); }
__device__ __forceinline__ float h2f_hi(unsigned v) { return __int_as_float((v >> 3) & 0x1FFFE000u); }

// ---------------- degree histogram ----------------
__global__ void k_zero_cnt() {
    int i = blockIdx.x * blockDim.x + threadIdx.x;
    if (i < N_NODES) g_cnt[i] = 0;
}

__global__ void k_hist(const int4* __restrict__ dst4) {
    int i = blockIdx.x * blockDim.x + threadIdx.x;   // N_EDGES/4 threads
    int4 d = __ldg(&dst4[i]);
    atomicAdd(&g_cnt[d.x], 1);
    atomicAdd(&g_cnt[d.y], 1);
    atomicAdd(&g_cnt[d.z], 1);
    atomicAdd(&g_cnt[d.w], 1);
}

// ---------------- exclusive scan over 100k counts (2 kernels) ----------------
__global__ void k_scan_blocks() {
    __shared__ int s[1024];
    int tid = threadIdx.x;
    int i = blockIdx.x * 1024 + tid;
    int v = (i < N_NODES) ? g_cnt[i] : 0;
    s[tid] = v;
    __syncthreads();
    for (int off = 1; off < 1024; off <<= 1) {
        int t = (tid >= off) ? s[tid - off] : 0;
        __syncthreads();
        s[tid] += t;
        __syncthreads();
    }
    if (i < N_NODES) g_rowptr[i] = s[tid] - v;   // exclusive within block
    if (tid == 1023) g_bsums[blockIdx.x] = s[1023];
}

__global__ void k_scan_add() {
    __shared__ int s_pre;
    int tid = threadIdx.x;
    if (tid < 32) {
        int acc = 0;
        for (int b = tid; b < blockIdx.x; b += 32) acc += g_bsums[b];
        for (int off = 16; off > 0; off >>= 1) acc += __shfl_xor_sync(0xffffffffu, acc, off);
        if (tid == 0) s_pre = acc;
    }
    __syncthreads();
    int i = blockIdx.x * 1024 + tid;
    if (i < N_NODES) {
        g_rowptr[i] += s_pre;
        g_dinv[i] = rsqrtf((float)(g_cnt[i] + 1));   // +1 self loop
        g_fill[i] = 0;
    }
    if (i == 0) g_rowptr[N_NODES] = N_EDGES;
}

// ---------------- CSR fill (packed {src, w}) ----------------
__global__ void k_fill(const int4* __restrict__ src4, const int4* __restrict__ dst4) {
    int i = blockIdx.x * blockDim.x + threadIdx.x;   // N_EDGES/4 threads
    int4 s = __ldg(&src4[i]);
    int4 d = __ldg(&dst4[i]);
    {
        int pos = g_rowptr[d.x] + atomicAdd(&g_fill[d.x], 1);
        g_csr[pos] = make_int2(s.x, __float_as_int(g_dinv[s.x] * g_dinv[d.x]));
    }
    {
        int pos = g_rowptr[d.y] + atomicAdd(&g_fill[d.y], 1);
        g_csr[pos] = make_int2(s.y, __float_as_int(g_dinv[s.y] * g_dinv[d.y]));
    }
    {
        int pos = g_rowptr[d.z] + atomicAdd(&g_fill[d.z], 1);
        g_csr[pos] = make_int2(s.z, __float_as_int(g_dinv[s.z] * g_dinv[d.z]));
    }
    {
        int pos = g_rowptr[d.w] + atomicAdd(&g_fill[d.w], 1);
        g_csr[pos] = make_int2(s.w, __float_as_int(g_dinv[s.w] * g_dinv[d.w]));
    }
}

// ---------------- layer 1 fused: agg(x,16) then @W1[16,64]+b1, relu -> h16a --
__global__ void k_agg16_mm1(const float* __restrict__ x,
                            const float* __restrict__ W1, const float* __restrict__ b1) {
    __shared__ float2 sW[16 * 32];
    __shared__ float2 sB[32];
    int tid = threadIdx.x;
    for (int idx = tid; idx < 16 * 32; idx += 256) {
        int k = idx >> 5, l = idx & 31;
        sW[idx] = make_float2(__ldg(&W1[k * 64 + 2 * l]), __ldg(&W1[k * 64 + 2 * l + 1]));
    }
    if (tid < 32) sB[tid] = make_float2(__ldg(&b1[2 * tid]), __ldg(&b1[2 * tid + 1]));
    __syncthreads();

    int w = (blockIdx.x * 256 + tid) >> 5;
    if (w >= N_NODES) return;
    int lane = tid & 31;
    int sub = lane >> 4, c = lane & 15;
    int e0 = __ldg(&g_rowptr[w]), e1 = __ldg(&g_rowptr[w + 1]);
    float dv = g_dinv[w];
    float a = (sub == 0) ? __ldg(&x[(size_t)w * 16 + c]) * dv * dv : 0.f;  // self loop
    int e = e0 + sub;
    for (; e + 2 < e1; e += 4) {             // 2 edges per sub in flight
        int2 c0 = __ldg(&g_csr[e]);
        int2 c1 = __ldg(&g_csr[e + 2]);
        float v0 = __ldg(&x[(size_t)c0.x * 16 + c]);
        float v1 = __ldg(&x[(size_t)c1.x * 16 + c]);
        a = fmaf(v0, __int_as_float(c0.y), a);
        a = fmaf(v1, __int_as_float(c1.y), a);
    }
    if (e < e1) {
        int2 cw = __ldg(&g_csr[e]);
        a = fmaf(__ldg(&x[(size_t)cw.x * 16 + c]), __int_as_float(cw.y), a);
    }
    a += __shfl_xor_sync(0xffffffffu, a, 16);    // every lane has a[c], c = lane&15

    // mm 16 -> 64: lane computes cols {2*lane, 2*lane+1}
    float2 acc = sB[lane];
#pragma unroll
    for (int k = 0; k < 16; k++) {
        float ak = __shfl_sync(0xffffffffu, a, k);
        float2 wv = sW[k * 32 + lane];
        acc.x = fmaf(ak, wv.x, acc.x);
        acc.y = fmaf(ak, wv.y, acc.y);
    }
    __half2 hv = __floats2half2_rn(fmaxf(acc.x, 0.f), fmaxf(acc.y, 0.f));
    ((__half2*)g_h16a)[(size_t)w * 32 + lane] = hv;
}

// ---------------- 64-wide aggregation over fp16 activations -> bufa fp32 -----
template <int SRC>
__global__ void k_agg64() {
    const __half* __restrict__ h = (SRC == 0) ? g_h16a : g_h16b;
    int w = (blockIdx.x * 256 + threadIdx.x) >> 5;
    if (w >= N_NODES) return;
    int lane = threadIdx.x & 31;
    int sub = lane >> 4, t = lane & 15;   // lane covers cols 4t..4t+3 of its sub's edge
    int e0 = __ldg(&g_rowptr[w]), e1 = __ldg(&g_rowptr[w + 1]);
    float dv = g_dinv[w];

    // self loop (sub0 only contributes; sub1 weight 0)
    uint2 sv = __ldg((const uint2*)(h + (size_t)w * 64) + t);
    float ws = (sub == 0) ? dv * dv * 0x1p112f : 0.f;
    float4 acc;
    acc.x = h2f_lo(sv.x) * ws;
    acc.y = h2f_hi(sv.x) * ws;
    acc.z = h2f_lo(sv.y) * ws;
    acc.w = h2f_hi(sv.y) * ws;

    int e = e0;
    if (e < e1 && (e & 1)) {     // peel to even alignment for int4 csr loads
        int2 cw = __ldg(&g_csr[e]);
        float wv = (sub == 0) ? __int_as_float(cw.y) * 0x1p112f : 0.f;
        uint2 f = __ldg((const uint2*)(h + (size_t)cw.x * 64) + t);
        acc.x = fmaf(h2f_lo(f.x), wv, acc.x);
        acc.y = fmaf(h2f_hi(f.x), wv, acc.y);
        acc.z = fmaf(h2f_lo(f.y), wv, acc.z);
        acc.w = fmaf(h2f_hi(f.y), wv, acc.w);
        e++;
    }
    for (; e + 4 <= e1; e += 4) {         // 4 edges: 2 int4 csr + 2 feature LDG per lane
        int4 p0 = __ldg((const int4*)g_csr + (e >> 1));
        int4 p1 = __ldg((const int4*)g_csr + (e >> 1) + 1);
        int   s0 = sub ? p0.z : p0.x;
        float w0 = __int_as_float(sub ? p0.w : p0.y) * 0x1p112f;
        int   s1 = sub ? p1.z : p1.x;
        float w1 = __int_as_float(sub ? p1.w : p1.y) * 0x1p112f;
        uint2 f0 = __ldg((const uint2*)(h + (size_t)s0 * 64) + t);
        uint2 f1 = __ldg((const uint2*)(h + (size_t)s1 * 64) + t);
        acc.x = fmaf(h2f_lo(f0.x), w0, acc.x);
        acc.y = fmaf(h2f_hi(f0.x), w0, acc.y);
        acc.z = fmaf(h2f_lo(f0.y), w0, acc.z);
        acc.w = fmaf(h2f_hi(f0.y), w0, acc.w);
        acc.x = fmaf(h2f_lo(f1.x), w1, acc.x);
        acc.y = fmaf(h2f_hi(f1.x), w1, acc.y);
        acc.z = fmaf(h2f_lo(f1.y), w1, acc.z);
        acc.w = fmaf(h2f_hi(f1.y), w1, acc.w);
    }
    if (e + 2 <= e1) {                    // one pair
        int4 p0 = __ldg((const int4*)g_csr + (e >> 1));
        int   s0 = sub ? p0.z : p0.x;
        float w0 = __int_as_float(sub ? p0.w : p0.y) * 0x1p112f;
        uint2 f0 = __ldg((const uint2*)(h + (size_t)s0 * 64) + t);
        acc.x = fmaf(h2f_lo(f0.x), w0, acc.x);
        acc.y = fmaf(h2f_hi(f0.x), w0, acc.y);
        acc.z = fmaf(h2f_lo(f0.y), w0, acc.z);
        acc.w = fmaf(h2f_hi(f0.y), w0, acc.w);
        e += 2;
    }
    if (e < e1) {                         // final single
        int2 cw = __ldg(&g_csr[e]);
        float wv = (sub == 0) ? __int_as_float(cw.y) * 0x1p112f : 0.f;
        uint2 f = __ldg((const uint2*)(h + (size_t)cw.x * 64) + t);
        acc.x = fmaf(h2f_lo(f.x), wv, acc.x);
        acc.y = fmaf(h2f_hi(f.x), wv, acc.y);
        acc.z = fmaf(h2f_lo(f.y), wv, acc.z);
        acc.w = fmaf(h2f_hi(f.y), wv, acc.w);
    }
    // combine the two 16-lane halves
    acc.x += __shfl_xor_sync(0xffffffffu, acc.x, 16);
    acc.y += __shfl_xor_sync(0xffffffffu, acc.y, 16);
    acc.z += __shfl_xor_sync(0xffffffffu, acc.z, 16);
    acc.w += __shfl_xor_sync(0xffffffffu, acc.w, 16);
    if (sub == 0) ((float4*)g_bufa)[(size_t)w * 16 + t] = acc;
}

// ---------------- matmul 64x64 + bias + relu: bufa -> fp16 buffer ------------
template <int DST>
__global__ void k_mm64(const float* __restrict__ Wm, const float* __restrict__ bv) {
    __half* __restrict__ out = (DST == 0) ? g_h16a : g_h16b;
    __shared__ float4 sIn[64 * 16];
    int tid = threadIdx.x;           // 256
    int row0 = blockIdx.x * 64;
    int col = tid & 63;
    float wreg[64];
#pragma unroll
    for (int k = 0; k < 64; k++) wreg[k] = __ldg(&Wm[k * 64 + col]);
    float bias = __ldg(&bv[col]);
    int nrows = min(64, N_NODES - row0);
    for (int idx = tid; idx < nrows * 16; idx += 256)
        sIn[idx] = __ldg((const float4*)g_bufa + (size_t)row0 * 16 + idx);
    __syncthreads();
    int rg = tid >> 6;
    for (int r = rg; r < nrows; r += 4) {
        float acc = bias;
#pragma unroll
        for (int k4 = 0; k4 < 16; k4++) {
            float4 v = sIn[r * 16 + k4];
            acc = fmaf(v.x, wreg[4 * k4 + 0], acc);
            acc = fmaf(v.y, wreg[4 * k4 + 1], acc);
            acc = fmaf(v.z, wreg[4 * k4 + 2], acc);
            acc = fmaf(v.w, wreg[4 * k4 + 3], acc);
        }
        out[(size_t)(row0 + r) * 64 + col] = __float2half_rn(fmaxf(acc, 0.f));
    }
}

// ---------------- mean pool per graph (batch sorted); reads g_h16a -----------
__global__ void k_pool(const int* __restrict__ batch) {
    int g = blockIdx.x;
    int lo = 0, hi = N_NODES;
    while (lo < hi) { int mid = (lo + hi) >> 1; if (__ldg(&batch[mid]) < g) lo = mid + 1; else hi = mid; }
    int start = lo;
    lo = start; hi = N_NODES;
    while (lo < hi) { int mid = (lo + hi) >> 1; if (__ldg(&batch[mid]) < g + 1) lo = mid + 1; else hi = mid; }
    int end = lo;

    __shared__ float2 sp[8][32];
    int cp = threadIdx.x & 31, rg = threadIdx.x >> 5;
    float2 acc = make_float2(0.f, 0.f);
    const __half2* h2 = (const __half2*)g_h16a;
    for (int r = start + rg; r < end; r += 8) {
        float2 f = __half22float2(h2[(size_t)r * 32 + cp]);
        acc.x += f.x; acc.y += f.y;
    }
    sp[rg][cp] = acc;
    __syncthreads();
    if (rg == 0) {
        float2 t = sp[0][cp];
#pragma unroll
        for (int i = 1; i < 8; i++) { t.x += sp[i][cp].x; t.y += sp[i][cp].y; }
        float cnt = (float)(end - start);
        if (cnt < 1.f) cnt = 1.f;
        ((float2*)g_pool)[g * 32 + cp] = make_float2(t.x / cnt, t.y / cnt);
    }
}

// ---------------- MLP head ----------------
__global__ void k_head(const float* __restrict__ Wf1, const float* __restrict__ bf1,
                       const float* __restrict__ Wf2, const float* __restrict__ bf2,
                       float* __restrict__ out) {
    int g = threadIdx.x;
    if (g >= N_GRAPHS) return;
    float p[64];
#pragma unroll
    for (int k = 0; k < 64; k++) p[k] = g_pool[g * 64 + k];
    float o = __ldg(&bf2[0]);
#pragma unroll 4
    for (int j = 0; j < 32; j++) {
        float hj = __ldg(&bf1[j]);
#pragma unroll
        for (int k = 0; k < 64; k++) hj = fmaf(p[k], __ldg(&Wf1[k * 32 + j]), hj);
        o = fmaf(fmaxf(hj, 0.f), __ldg(&Wf2[j]), o);
    }
    out[g] = o;
}

// ---------------- launch ----------------
extern "C" void kernel_launch(void* const* d_in, const int* in_sizes, int n_in,
                              void* d_out, int out_size) {
    const float* x   = (const float*)d_in[0];
    const int*   ei  = (const int*)d_in[1];
    const int4*  src4 = (const int4*)ei;
    const int4*  dst4 = (const int4*)(ei + N_EDGES);
    const int*   batch = (const int*)d_in[3];
    const float* W1 = (const float*)d_in[4];  const float* b1 = (const float*)d_in[5];
    const float* W2 = (const float*)d_in[6];  const float* b2 = (const float*)d_in[7];
    const float* W3 = (const float*)d_in[8];  const float* b3 = (const float*)d_in[9];
    const float* Wf1 = (const float*)d_in[10]; const float* bf1 = (const float*)d_in[11];
    const float* Wf2 = (const float*)d_in[12]; const float* bf2 = (const float*)d_in[13];
    float* out = (float*)d_out;

    const int nb_scan = (N_NODES + 1023) / 1024;       // 98
    const int eb4 = (N_EDGES / 4) / 256;               // 3125
    const int wb = (N_NODES * 32 + 255) / 256;         // one warp per node: 12500
    const int mb = (N_NODES + 63) / 64;                // 1563

    k_zero_cnt<<<(N_NODES + 255) / 256, 256>>>();
    k_hist<<<eb4, 256>>>(dst4);
    k_scan_blocks<<<nb_scan, 1024>>>();
    k_scan_add<<<nb_scan, 1024>>>();
    k_fill<<<eb4, 256>>>(src4, dst4);

    k_agg16_mm1<<<wb, 256>>>(x, W1, b1);   // layer 1 fused -> h16a
    k_agg64<0><<<wb, 256>>>();             // gather h16a -> bufa
    k_mm64<1><<<mb, 256>>>(W2, b2);        // bufa@W2 -> h16b
    k_agg64<1><<<wb, 256>>>();             // gather h16b -> bufa
    k_mm64<0><<<mb, 256>>>(W3, b3);        // bufa@W3 -> h16a

    k_pool<<<N_GRAPHS, 256>>>(batch);
    k_head<<<1, 128>>>(Wf1, bf1, Wf2, bf2, out);
}

// round 5
// speedup vs baseline: 1.6358x; 1.6358x over previous
#include <cuda_runtime.h>
#include <cuda_fp16.h>

#define N_NODES  100000
#define N_EDGES  3200000
#define N_GRAPHS 128

// ---------------- scratch (static device globals; no runtime alloc) ----------
__device__ int   g_cnt[N_NODES];
__device__ int   g_rowptr[N_NODES + 1];
__device__ int   g_fill[N_NODES];
__device__ int   g_bsums[128];
__device__ float g_dinv[N_NODES];
__device__ __align__(16) int2 g_csr[N_EDGES];      // {src, float_bits(dinv[src])}
__device__ __align__(16) float g_bufa[N_NODES * 64];   // agg output (fp32, sequential)
__device__ __align__(16) __half g_h16a[N_NODES * 64];  // activations fp16 (layers 1,3)
__device__ __align__(16) __half g_h16b[N_NODES * 64];  // activations fp16 (layer 2)
__device__ __align__(16) float g_pool[N_GRAPHS * 64];

// half(nonneg)->float bit tricks; result is 2^-112 * true_value; compensated once
// per node by multiplying the accumulator with 2^112. Exact (incl. subnormals)
// because activations are post-ReLU (sign bit 0).
__device__ __forceinline__ float h2f_lo(unsigned v) { return __int_as_float((v & 0xffffu) << 13); }
__device__ __forceinline__ float h2f_hi(unsigned v) { return __int_as_float((v >> 3) & 0x1FFFE000u); }

// ---------------- degree histogram ----------------
__global__ void k_zero_cnt() {
    int i = blockIdx.x * blockDim.x + threadIdx.x;
    if (i < N_NODES) g_cnt[i] = 0;
}

__global__ void k_hist(const int4* __restrict__ dst4) {
    int i = blockIdx.x * blockDim.x + threadIdx.x;   // N_EDGES/4 threads
    int4 d = __ldg(&dst4[i]);
    atomicAdd(&g_cnt[d.x], 1);
    atomicAdd(&g_cnt[d.y], 1);
    atomicAdd(&g_cnt[d.z], 1);
    atomicAdd(&g_cnt[d.w], 1);
}

// ---------------- exclusive scan over 100k counts (2 kernels) ----------------
__global__ void k_scan_blocks() {
    __shared__ int s[1024];
    int tid = threadIdx.x;
    int i = blockIdx.x * 1024 + tid;
    int v = (i < N_NODES) ? g_cnt[i] : 0;
    s[tid] = v;
    __syncthreads();
    for (int off = 1; off < 1024; off <<= 1) {
        int t = (tid >= off) ? s[tid - off] : 0;
        __syncthreads();
        s[tid] += t;
        __syncthreads();
    }
    if (i < N_NODES) g_rowptr[i] = s[tid] - v;   // exclusive within block
    if (tid == 1023) g_bsums[blockIdx.x] = s[1023];
}

__global__ void k_scan_add() {
    __shared__ int s_pre;
    int tid = threadIdx.x;
    if (tid < 32) {
        int acc = 0;
        for (int b = tid; b < blockIdx.x; b += 32) acc += g_bsums[b];
        for (int off = 16; off > 0; off >>= 1) acc += __shfl_xor_sync(0xffffffffu, acc, off);
        if (tid == 0) s_pre = acc;
    }
    __syncthreads();
    int i = blockIdx.x * 1024 + tid;
    if (i < N_NODES) {
        g_rowptr[i] += s_pre;
        g_dinv[i] = rsqrtf((float)(g_cnt[i] + 1));   // +1 self loop
        g_fill[i] = 0;
    }
    if (i == 0) g_rowptr[N_NODES] = N_EDGES;
}

// ---------------- CSR fill (packed {src, dinv[src]}) ----------------
// dinv[dst] is applied per-node at the end of aggregation (it factors out).
__global__ void k_fill(const int4* __restrict__ src4, const int4* __restrict__ dst4) {
    int i = blockIdx.x * blockDim.x + threadIdx.x;   // N_EDGES/4 threads
    int4 s = __ldg(&src4[i]);
    int4 d = __ldg(&dst4[i]);
    {
        int pos = g_rowptr[d.x] + atomicAdd(&g_fill[d.x], 1);
        g_csr[pos] = make_int2(s.x, __float_as_int(g_dinv[s.x]));
    }
    {
        int pos = g_rowptr[d.y] + atomicAdd(&g_fill[d.y], 1);
        g_csr[pos] = make_int2(s.y, __float_as_int(g_dinv[s.y]));
    }
    {
        int pos = g_rowptr[d.z] + atomicAdd(&g_fill[d.z], 1);
        g_csr[pos] = make_int2(s.z, __float_as_int(g_dinv[s.z]));
    }
    {
        int pos = g_rowptr[d.w] + atomicAdd(&g_fill[d.w], 1);
        g_csr[pos] = make_int2(s.w, __float_as_int(g_dinv[s.w]));
    }
}

// ---------------- layer 1 fused: agg(x,16) then @W1[16,64]+b1, relu -> h16a --
// warp per node; sub 0 handles edges e0,e0+2,..., sub 1 handles e0+1,e0+3,...
__global__ void k_agg16_mm1(const float* __restrict__ x,
                            const float* __restrict__ W1, const float* __restrict__ b1) {
    __shared__ float2 sW[16 * 32];
    __shared__ float2 sB[32];
    int tid = threadIdx.x;
    for (int idx = tid; idx < 16 * 32; idx += 256) {
        int k = idx >> 5, l = idx & 31;
        sW[idx] = make_float2(__ldg(&W1[k * 64 + 2 * l]), __ldg(&W1[k * 64 + 2 * l + 1]));
    }
    if (tid < 32) sB[tid] = make_float2(__ldg(&b1[2 * tid]), __ldg(&b1[2 * tid + 1]));
    __syncthreads();

    int w = (blockIdx.x * 256 + tid) >> 5;
    if (w >= N_NODES) return;
    int lane = tid & 31;
    int sub = lane >> 4, c = lane & 15;
    int e0 = __ldg(&g_rowptr[w]), e1 = __ldg(&g_rowptr[w + 1]);
    float dv = g_dinv[w];
    // self loop: x[w]*dv here, *dv again at the end -> dv^2
    float a = (sub == 0) ? __ldg(&x[(size_t)w * 16 + c]) * dv : 0.f;
    int k = e0 + sub;
    for (; k + 6 < e1; k += 8) {       // 4 edges per sub in flight
        int2 c0 = __ldg(&g_csr[k]);
        int2 c1 = __ldg(&g_csr[k + 2]);
        int2 c2 = __ldg(&g_csr[k + 4]);
        int2 c3 = __ldg(&g_csr[k + 6]);
        float v0 = __ldg(&x[(size_t)c0.x * 16 + c]);
        float v1 = __ldg(&x[(size_t)c1.x * 16 + c]);
        float v2 = __ldg(&x[(size_t)c2.x * 16 + c]);
        float v3 = __ldg(&x[(size_t)c3.x * 16 + c]);
        a = fmaf(v0, __int_as_float(c0.y), a);
        a = fmaf(v1, __int_as_float(c1.y), a);
        a = fmaf(v2, __int_as_float(c2.y), a);
        a = fmaf(v3, __int_as_float(c3.y), a);
    }
    for (; k < e1; k += 2) {
        int2 cw = __ldg(&g_csr[k]);
        a = fmaf(__ldg(&x[(size_t)cw.x * 16 + c]), __int_as_float(cw.y), a);
    }
    a *= dv;                                     // dinv[dst] factored out
    a += __shfl_xor_sync(0xffffffffu, a, 16);    // combine subs; lane has a[lane&15]

    // mm 16 -> 64: lane computes cols {2*lane, 2*lane+1}
    float2 acc = sB[lane];
#pragma unroll
    for (int kk = 0; kk < 16; kk++) {
        float ak = __shfl_sync(0xffffffffu, a, kk);
        float2 wv = sW[kk * 32 + lane];
        acc.x = fmaf(ak, wv.x, acc.x);
        acc.y = fmaf(ak, wv.y, acc.y);
    }
    __half2 hv = __floats2half2_rn(fmaxf(acc.x, 0.f), fmaxf(acc.y, 0.f));
    ((__half2*)g_h16a)[(size_t)w * 32 + lane] = hv;
}

// ---------------- 64-wide aggregation over fp16 activations -> bufa fp32 -----
// warp per node; sub handles every-other edge; lane covers 4 cols (uint2 of halves).
template <int SRC>
__global__ void k_agg64() {
    const __half* __restrict__ h = (SRC == 0) ? g_h16a : g_h16b;
    int w = (blockIdx.x * 256 + threadIdx.x) >> 5;
    if (w >= N_NODES) return;
    int lane = threadIdx.x & 31;
    int sub = lane >> 4, t = lane & 15;
    int e0 = __ldg(&g_rowptr[w]), e1 = __ldg(&g_rowptr[w + 1]);
    float dv = g_dinv[w];

    // self loop contribution (sub0 only; *dv here, *(dv*2^112) at the end -> dv^2)
    uint2 sv = __ldg((const uint2*)(h + (size_t)w * 64) + t);
    float ws = (sub == 0) ? dv : 0.f;
    float4 acc;
    acc.x = h2f_lo(sv.x) * ws;
    acc.y = h2f_hi(sv.x) * ws;
    acc.z = h2f_lo(sv.y) * ws;
    acc.w = h2f_hi(sv.y) * ws;

    int k = e0 + sub;
    for (; k + 6 < e1; k += 8) {       // 4 edges per sub: 4 csr + 4 feature loads in flight
        int2 c0 = __ldg(&g_csr[k]);
        int2 c1 = __ldg(&g_csr[k + 2]);
        int2 c2 = __ldg(&g_csr[k + 4]);
        int2 c3 = __ldg(&g_csr[k + 6]);
        uint2 f0 = __ldg((const uint2*)(h + (size_t)c0.x * 64) + t);
        uint2 f1 = __ldg((const uint2*)(h + (size_t)c1.x * 64) + t);
        uint2 f2 = __ldg((const uint2*)(h + (size_t)c2.x * 64) + t);
        uint2 f3 = __ldg((const uint2*)(h + (size_t)c3.x * 64) + t);
        float w0 = __int_as_float(c0.y), w1 = __int_as_float(c1.y);
        float w2 = __int_as_float(c2.y), w3 = __int_as_float(c3.y);
        acc.x = fmaf(h2f_lo(f0.x), w0, acc.x);
        acc.y = fmaf(h2f_hi(f0.x), w0, acc.y);
        acc.z = fmaf(h2f_lo(f0.y), w0, acc.z);
        acc.w = fmaf(h2f_hi(f0.y), w0, acc.w);
        acc.x = fmaf(h2f_lo(f1.x), w1, acc.x);
        acc.y = fmaf(h2f_hi(f1.x), w1, acc.y);
        acc.z = fmaf(h2f_lo(f1.y), w1, acc.z);
        acc.w = fmaf(h2f_hi(f1.y), w1, acc.w);
        acc.x = fmaf(h2f_lo(f2.x), w2, acc.x);
        acc.y = fmaf(h2f_hi(f2.x), w2, acc.y);
        acc.z = fmaf(h2f_lo(f2.y), w2, acc.z);
        acc.w = fmaf(h2f_hi(f2.y), w2, acc.w);
        acc.x = fmaf(h2f_lo(f3.x), w3, acc.x);
        acc.y = fmaf(h2f_hi(f3.x), w3, acc.y);
        acc.z = fmaf(h2f_lo(f3.y), w3, acc.z);
        acc.w = fmaf(h2f_hi(f3.y), w3, acc.w);
    }
    for (; k < e1; k += 2) {
        int2 cw = __ldg(&g_csr[k]);
        float wv = __int_as_float(cw.y);
        uint2 f = __ldg((const uint2*)(h + (size_t)cw.x * 64) + t);
        acc.x = fmaf(h2f_lo(f.x), wv, acc.x);
        acc.y = fmaf(h2f_hi(f.x), wv, acc.y);
        acc.z = fmaf(h2f_lo(f.y), wv, acc.z);
        acc.w = fmaf(h2f_hi(f.y), wv, acc.w);
    }
    // apply dinv[dst] and fp16-decode compensation once
    float fs = dv * 0x1p112f;
    acc.x *= fs; acc.y *= fs; acc.z *= fs; acc.w *= fs;
    // combine the two 16-lane halves
    acc.x += __shfl_xor_sync(0xffffffffu, acc.x, 16);
    acc.y += __shfl_xor_sync(0xffffffffu, acc.y, 16);
    acc.z += __shfl_xor_sync(0xffffffffu, acc.z, 16);
    acc.w += __shfl_xor_sync(0xffffffffu, acc.w, 16);
    if (sub == 0) ((float4*)g_bufa)[(size_t)w * 16 + t] = acc;
}

// ---------------- matmul 64x64 + bias + relu: bufa -> fp16 buffer ------------
template <int DST>
__global__ void k_mm64(const float* __restrict__ Wm, const float* __restrict__ bv) {
    __half* __restrict__ out = (DST == 0) ? g_h16a : g_h16b;
    __shared__ float4 sIn[64 * 16];
    int tid = threadIdx.x;           // 256
    int row0 = blockIdx.x * 64;
    int col = tid & 63;
    float wreg[64];
#pragma unroll
    for (int k = 0; k < 64; k++) wreg[k] = __ldg(&Wm[k * 64 + col]);
    float bias = __ldg(&bv[col]);
    int nrows = min(64, N_NODES - row0);
    for (int idx = tid; idx < nrows * 16; idx += 256)
        sIn[idx] = __ldg((const float4*)g_bufa + (size_t)row0 * 16 + idx);
    __syncthreads();
    int rg = tid >> 6;
    for (int r = rg; r < nrows; r += 4) {
        float acc = bias;
#pragma unroll
        for (int k4 = 0; k4 < 16; k4++) {
            float4 v = sIn[r * 16 + k4];
            acc = fmaf(v.x, wreg[4 * k4 + 0], acc);
            acc = fmaf(v.y, wreg[4 * k4 + 1], acc);
            acc = fmaf(v.z, wreg[4 * k4 + 2], acc);
            acc = fmaf(v.w, wreg[4 * k4 + 3], acc);
        }
        out[(size_t)(row0 + r) * 64 + col] = __float2half_rn(fmaxf(acc, 0.f));
    }
}

// ---------------- mean pool per graph (batch sorted); reads g_h16a -----------
__global__ void k_pool(const int* __restrict__ batch) {
    int g = blockIdx.x;
    int lo = 0, hi = N_NODES;
    while (lo < hi) { int mid = (lo + hi) >> 1; if (__ldg(&batch[mid]) < g) lo = mid + 1; else hi = mid; }
    int start = lo;
    lo = start; hi = N_NODES;
    while (lo < hi) { int mid = (lo + hi) >> 1; if (__ldg(&batch[mid]) < g + 1) lo = mid + 1; else hi = mid; }
    int end = lo;

    __shared__ float2 sp[8][32];
    int cp = threadIdx.x & 31, rg = threadIdx.x >> 5;
    float2 acc = make_float2(0.f, 0.f);
    const __half2* h2 = (const __half2*)g_h16a;
    for (int r = start + rg; r < end; r += 8) {
        float2 f = __half22float2(h2[(size_t)r * 32 + cp]);
        acc.x += f.x; acc.y += f.y;
    }
    sp[rg][cp] = acc;
    __syncthreads();
    if (rg == 0) {
        float2 t = sp[0][cp];
#pragma unroll
        for (int i = 1; i < 8; i++) { t.x += sp[i][cp].x; t.y += sp[i][cp].y; }
        float cnt = (float)(end - start);
        if (cnt < 1.f) cnt = 1.f;
        ((float2*)g_pool)[g * 32 + cp] = make_float2(t.x / cnt, t.y / cnt);
    }
}

// ---------------- MLP head ----------------
__global__ void k_head(const float* __restrict__ Wf1, const float* __restrict__ bf1,
                       const float* __restrict__ Wf2, const float* __restrict__ bf2,
                       float* __restrict__ out) {
    int g = threadIdx.x;
    if (g >= N_GRAPHS) return;
    float p[64];
#pragma unroll
    for (int k = 0; k < 64; k++) p[k] = g_pool[g * 64 + k];
    float o = __ldg(&bf2[0]);
#pragma unroll 4
    for (int j = 0; j < 32; j++) {
        float hj = __ldg(&bf1[j]);
#pragma unroll
        for (int k = 0; k < 64; k++) hj = fmaf(p[k], __ldg(&Wf1[k * 32 + j]), hj);
        o = fmaf(fmaxf(hj, 0.f), __ldg(&Wf2[j]), o);
    }
    out[g] = o;
}

// ---------------- launch ----------------
extern "C" void kernel_launch(void* const* d_in, const int* in_sizes, int n_in,
                              void* d_out, int out_size) {
    const float* x   = (const float*)d_in[0];
    const int*   ei  = (const int*)d_in[1];
    const int4*  src4 = (const int4*)ei;
    const int4*  dst4 = (const int4*)(ei + N_EDGES);
    const int*   batch = (const int*)d_in[3];
    const float* W1 = (const float*)d_in[4];  const float* b1 = (const float*)d_in[5];
    const float* W2 = (const float*)d_in[6];  const float* b2 = (const float*)d_in[7];
    const float* W3 = (const float*)d_in[8];  const float* b3 = (const float*)d_in[9];
    const float* Wf1 = (const float*)d_in[10]; const float* bf1 = (const float*)d_in[11];
    const float* Wf2 = (const float*)d_in[12]; const float* bf2 = (const float*)d_in[13];
    float* out = (float*)d_out;

    const int nb_scan = (N_NODES + 1023) / 1024;       // 98
    const int eb4 = (N_EDGES / 4) / 256;               // 3125
    const int wb = (N_NODES * 32 + 255) / 256;         // one warp per node: 12500
    const int mb = (N_NODES + 63) / 64;                // 1563

    k_zero_cnt<<<(N_NODES + 255) / 256, 256>>>();
    k_hist<<<eb4, 256>>>(dst4);
    k_scan_blocks<<<nb_scan, 1024>>>();
    k_scan_add<<<nb_scan, 1024>>>();
    k_fill<<<eb4, 256>>>(src4, dst4);

    k_agg16_mm1<<<wb, 256>>>(x, W1, b1);   // layer 1 fused -> h16a
    k_agg64<0><<<wb, 256>>>();             // gather h16a -> bufa
    k_mm64<1><<<mb, 256>>>(W2, b2);        // bufa@W2 -> h16b
    k_agg64<1><<<wb, 256>>>();             // gather h16b -> bufa
    k_mm64<0><<<mb, 256>>>(W3, b3);        // bufa@W3 -> h16a

    k_pool<<<N_GRAPHS, 256>>>(batch);
    k_head<<<1, 128>>>(Wf1, bf1, Wf2, bf2, out);
}